// round 5
// baseline (speedup 1.0000x reference)
#include <cuda_runtime.h>
#include <cuda_bf16.h>
#include <math_constants.h>

// Problem constants (fixed by the dataset):
//   N = 55440*1024 = 56,770,560 fp32; candidates L in [4,32] dividing N -> 20
//   P = lcm(candidates) = 110880, N / P = 512
#define NTOT   56770560
#define PP4    27720        // P/4 float4 positions per period
#define RSPLIT 16           // split the 512 repeats 16 ways
#define RCHUNK 32           // 512 / RSPLIT
#define NCAND  20
#define VPT    4            // float4 positions per thread
#define NBX    28           // ceil(27720 / (256*4)) ; last block partial (72 f4)
#define NBLK   (NBX * RSPLIT)   // 448 blocks, ~single wave @3/SM

// Scratch (__device__ globals; plain per-block stores -> no init required)
__device__ unsigned g_blk[NBLK][NCAND];  // per-block candidate maxima (float bits)
__device__ unsigned g_done;             // completion counter, self-resets to 0

// ---------------------------------------------------------------------------
// Single fused kernel, DRAM-locality layout:
//   warp w of block bx owns float4 window [bx*1024 + w*128, +128) (2KB).
//   load j (0..3): f4 index = windowBase + j*32 + lane -> four back-to-back
//   coalesced 512B loads = contiguous 2KB per warp per r-iteration; the block
//   covers 16KB contiguous. r strides by the period (PP4 float4s).
// Phase B: evaluate all 20 candidates on chunk-local (mn, mx) per position.
//   Valid since max over (p,r) = max over chunks of per-chunk candidate max,
//   and max_v |fl(v-c)| = max(fl(mx-c), fl(c-mn)) exactly (fl monotone,
//   sign-symmetric). pat = x[p % L], L literal after unroll.
// Phase C: shfl-butterfly warp reduce -> lane-0 shared atomics -> per-block
//   store to g_blk; fenced last-done block reduces, scores, argmax, writes 42
//   outputs. Counter self-resets for graph replay.
// ---------------------------------------------------------------------------
__global__ __launch_bounds__(256, 3) void pm_fused(const float4* __restrict__ x4,
                                                   float* __restrict__ out,
                                                   int out_size) {
    __shared__ float    s_pat[32];
    __shared__ unsigned s_max[NCAND];
    __shared__ bool     s_last;
    if (threadIdx.x < 32)    s_pat[threadIdx.x] = ((const float*)x4)[threadIdx.x];
    if (threadIdx.x < NCAND) s_max[threadIdx.x] = 0u;
    __syncthreads();

    const int LENS[NCAND] = {4,5,6,7,8,9,10,11,12,14,15,16,18,20,21,22,24,28,30,32};

    float acc[NCAND];
#pragma unroll
    for (int k = 0; k < NCAND; k++) acc[k] = 0.0f;

    int lane = threadIdx.x & 31;
    int w    = threadIdx.x >> 5;

    int  f4i[VPT];
    bool val[VPT];
#pragma unroll
    for (int j = 0; j < VPT; j++) {
        f4i[j] = blockIdx.x * 1024 + w * 128 + j * 32 + lane;
        val[j] = (f4i[j] < PP4);
    }

    float4 mn[VPT], mx[VPT];
#pragma unroll
    for (int j = 0; j < VPT; j++) {
        mn[j] = make_float4( CUDART_INF_F,  CUDART_INF_F,  CUDART_INF_F,  CUDART_INF_F);
        mx[j] = make_float4(-CUDART_INF_F, -CUDART_INF_F, -CUDART_INF_F, -CUDART_INF_F);
    }

    // --- Phase A: chunk-local min/max; warp reads contiguous 2KB per row ---
    const float4* base = x4 + (size_t)blockIdx.y * (RCHUNK * PP4);
    for (int r = 0; r < RCHUNK; r++) {
        const float4* row = base + (size_t)r * PP4;
#pragma unroll
        for (int j = 0; j < VPT; j++) {
            if (val[j]) {
                float4 u = __ldcs(row + f4i[j]);
                mn[j].x = fminf(mn[j].x, u.x); mx[j].x = fmaxf(mx[j].x, u.x);
                mn[j].y = fminf(mn[j].y, u.y); mx[j].y = fmaxf(mx[j].y, u.y);
                mn[j].z = fminf(mn[j].z, u.z); mx[j].z = fmaxf(mx[j].z, u.z);
                mn[j].w = fminf(mn[j].w, u.w); mx[j].w = fmaxf(mx[j].w, u.w);
            }
        }
    }

    // --- Phase B: 20-candidate fold on this thread's 16 scalar positions ---
#pragma unroll
    for (int j = 0; j < VPT; j++) {
        if (!val[j]) continue;
        float mnk[4] = {mn[j].x, mn[j].y, mn[j].z, mn[j].w};
        float mxk[4] = {mx[j].x, mx[j].y, mx[j].z, mx[j].w};
        int p0 = 4 * f4i[j];
#pragma unroll
        for (int q = 0; q < 4; q++) {
            int pp = p0 + q;
#pragma unroll
            for (int k = 0; k < NCAND; k++) {
                int   L   = LENS[k];                 // literal after unroll
                float ctr = s_pat[pp % L];
                float d   = fmaxf(mxk[q] - ctr, ctr - mnk[q]);
                acc[k]    = fmaxf(acc[k], d);
            }
        }
    }

    // --- Phase C: warp shfl reduce, lane-0 shared atomics, per-block store ---
#pragma unroll
    for (int k = 0; k < NCAND; k++) {
        float a = acc[k];
        a = fmaxf(a, __shfl_xor_sync(0xFFFFFFFFu, a, 16));
        a = fmaxf(a, __shfl_xor_sync(0xFFFFFFFFu, a, 8));
        a = fmaxf(a, __shfl_xor_sync(0xFFFFFFFFu, a, 4));
        a = fmaxf(a, __shfl_xor_sync(0xFFFFFFFFu, a, 2));
        a = fmaxf(a, __shfl_xor_sync(0xFFFFFFFFu, a, 1));
        acc[k] = a;
    }
    if (lane == 0) {
#pragma unroll
        for (int k = 0; k < NCAND; k++)
            atomicMax(&s_max[k], __float_as_uint(acc[k]));
    }
    __syncthreads();

    int bid = blockIdx.y * gridDim.x + blockIdx.x;
    if (threadIdx.x < NCAND)
        g_blk[bid][threadIdx.x] = s_max[threadIdx.x];

    __threadfence();   // publish g_blk before signaling completion
    if (threadIdx.x == 0) {
        unsigned prev = atomicAdd(&g_done, 1u);
        s_last = (prev == NBLK - 1);
    }
    __syncthreads();
    if (!s_last) return;

    // --- Finalize (one block): reduce g_blk, scores, argmax, outputs ---
    __threadfence();   // acquire all writers' g_blk stores
    __shared__ unsigned s_fin[NCAND];
    if (threadIdx.x == 0) g_done = 0u;            // reset for next replay
    if (threadIdx.x < NCAND) s_fin[threadIdx.x] = 0u;
    __syncthreads();

    if (threadIdx.x < 240) {                      // 12 groups x 20 candidates
        int g = threadIdx.x / NCAND;
        int k = threadIdx.x % NCAND;
        unsigned v = 0u;
        for (int b = g; b < NBLK; b += 12)
            v = max(v, g_blk[b][k]);
        atomicMax(&s_fin[k], v);
    }
    __syncthreads();

    if (threadIdx.x == 0) {
        float best = 0.0f;
        int   bidx = 0;
#pragma unroll
        for (int k = 0; k < NCAND; k++) {
            float md  = __uint_as_float(s_fin[k]);
            int   L   = LENS[k];
            float raw = (float)((double)(NTOT / L) / (double)L);
            float eff = (md < 0.01f) ? raw : 0.0f;
            if (k < out_size)      out[k]      = md;
            if (20 + k < out_size) out[20 + k] = eff;
            if (eff > best) { best = eff; bidx = k; }  // first max, like jnp.argmax
        }
        if (out_size > 40) out[40] = (float)bidx;
        if (out_size > 41) out[41] = best;
    }
}

// ---------------------------------------------------------------------------
extern "C" void kernel_launch(void* const* d_in, const int* in_sizes, int n_in,
                              void* d_out, int out_size) {
    const float* x = (const float*)d_in[0];
    float* out = (float*)d_out;

    dim3 grid(NBX, RSPLIT);
    pm_fused<<<grid, 256>>>((const float4*)x, out, out_size);
}

// round 6
// speedup vs baseline: 1.2312x; 1.2312x over previous
#include <cuda_runtime.h>
#include <cuda_bf16.h>
#include <math_constants.h>

// Problem constants (fixed by the dataset):
//   N = 55440*1024 = 56,770,560 fp32; candidates L in [4,32] dividing N -> 20
//   P = lcm(candidates) = 110880, N / P = 512
#define NTOT   56770560
#define PP4    27720        // P/4 float4 positions per period
#define RSPLIT 4            // split the 512 repeats 4 ways
#define RCHUNK 128          // 512 / RSPLIT
#define NCAND  20
#define NBX    109          // ceil(PP4 / 256)
#define NBLK   (NBX * RSPLIT)   // 436 blocks, single wave @3/SM

// Scratch (__device__ globals; plain per-block stores -> no init required)
__device__ unsigned g_blk[NBLK][NCAND];  // per-block candidate maxima (float bits)
__device__ unsigned g_done;             // completion counter, self-resets to 0

// ---------------------------------------------------------------------------
// Single fused kernel (R3 layout, deeper MLP, no barrier before loads).
// Phase A: thread t = one float4 period-position; chunk c = blockIdx.y.
//   128 loads strided by the period (PP4), unroll 16 -> deep LDG batches.
//   Warp loads are 512B coalesced; the 109 x-blocks of a chunk jointly cover
//   a full 443KB period row, 4 such fronts advance in parallel.
// Phase B: evaluate all 20 candidates on chunk-local (mn, mx). Valid since
//   max over (p,r) = max over chunks of per-chunk candidate max, and
//   max_v |fl(v-c)| = max(fl(mx-c), fl(c-mn)) exactly (fl monotone,
//   sign-symmetric). pat = x[p % L], L literal after unroll.
// Phase C: shfl-butterfly warp reduce (all threads alive, acc=0 for idle) ->
//   lane-0 shared atomics -> per-block store to g_blk; fenced last-done block
//   reduces, scores, argmax, writes 42 outputs. Counter self-resets.
// ---------------------------------------------------------------------------
__global__ __launch_bounds__(256, 3) void pm_fused(const float4* __restrict__ x4,
                                                   float* __restrict__ out,
                                                   int out_size) {
    __shared__ float    s_pat[32];
    __shared__ unsigned s_max[NCAND];
    __shared__ bool     s_last;

    const int LENS[NCAND] = {4,5,6,7,8,9,10,11,12,14,15,16,18,20,21,22,24,28,30,32};

    int  t    = blockIdx.x * 256 + threadIdx.x;
    bool live = (t < PP4);

    // --- Phase A first: no barrier between kernel entry and first LDG ---
    float4 mn = make_float4( CUDART_INF_F,  CUDART_INF_F,  CUDART_INF_F,  CUDART_INF_F);
    float4 mx = make_float4(-CUDART_INF_F, -CUDART_INF_F, -CUDART_INF_F, -CUDART_INF_F);
    if (live) {
        const float4* p = x4 + (size_t)blockIdx.y * (RCHUNK * PP4) + t;
#pragma unroll 16
        for (int r = 0; r < RCHUNK; r++) {
            float4 u = __ldcs(p + (size_t)r * PP4);
            mn.x = fminf(mn.x, u.x); mx.x = fmaxf(mx.x, u.x);
            mn.y = fminf(mn.y, u.y); mx.y = fmaxf(mx.y, u.y);
            mn.z = fminf(mn.z, u.z); mx.z = fmaxf(mx.z, u.z);
            mn.w = fminf(mn.w, u.w); mx.w = fmaxf(mx.w, u.w);
        }
    }

    // Pattern + reduction smem init (off the load critical path)
    if (threadIdx.x < 32)    s_pat[threadIdx.x] = ((const float*)x4)[threadIdx.x];
    if (threadIdx.x < NCAND) s_max[threadIdx.x] = 0u;
    __syncthreads();

    // --- Phase B: 20-candidate fold on this thread's 4 scalar positions ---
    float acc[NCAND];
#pragma unroll
    for (int k = 0; k < NCAND; k++) acc[k] = 0.0f;

    if (live) {
        float mnk[4] = {mn.x, mn.y, mn.z, mn.w};
        float mxk[4] = {mx.x, mx.y, mx.z, mx.w};
        int p0 = 4 * t;
#pragma unroll
        for (int j = 0; j < 4; j++) {
            int pp = p0 + j;
#pragma unroll
            for (int k = 0; k < NCAND; k++) {
                int   L   = LENS[k];                 // literal after unroll
                float ctr = s_pat[pp % L];
                float d   = fmaxf(mxk[j] - ctr, ctr - mnk[j]);
                acc[k]    = fmaxf(acc[k], d);
            }
        }
    }

    // --- Phase C: warp shfl reduce, lane-0 shared atomics, per-block store ---
#pragma unroll
    for (int k = 0; k < NCAND; k++) {
        float a = acc[k];
        a = fmaxf(a, __shfl_xor_sync(0xFFFFFFFFu, a, 16));
        a = fmaxf(a, __shfl_xor_sync(0xFFFFFFFFu, a, 8));
        a = fmaxf(a, __shfl_xor_sync(0xFFFFFFFFu, a, 4));
        a = fmaxf(a, __shfl_xor_sync(0xFFFFFFFFu, a, 2));
        a = fmaxf(a, __shfl_xor_sync(0xFFFFFFFFu, a, 1));
        acc[k] = a;
    }
    if ((threadIdx.x & 31) == 0) {
#pragma unroll
        for (int k = 0; k < NCAND; k++)
            atomicMax(&s_max[k], __float_as_uint(acc[k]));
    }
    __syncthreads();

    int bid = blockIdx.y * gridDim.x + blockIdx.x;
    if (threadIdx.x < NCAND)
        g_blk[bid][threadIdx.x] = s_max[threadIdx.x];

    __threadfence();   // publish g_blk before signaling completion
    if (threadIdx.x == 0) {
        unsigned prev = atomicAdd(&g_done, 1u);
        s_last = (prev == NBLK - 1);
    }
    __syncthreads();
    if (!s_last) return;

    // --- Finalize (one block): reduce g_blk, scores, argmax, outputs ---
    __threadfence();   // acquire all writers' g_blk stores
    __shared__ unsigned s_fin[NCAND];
    if (threadIdx.x == 0) g_done = 0u;            // reset for next replay
    if (threadIdx.x < NCAND) s_fin[threadIdx.x] = 0u;
    __syncthreads();

    if (threadIdx.x < 240) {                      // 12 groups x 20 candidates
        int g = threadIdx.x / NCAND;
        int k = threadIdx.x % NCAND;
        unsigned v = 0u;
        for (int b = g; b < NBLK; b += 12)
            v = max(v, g_blk[b][k]);
        atomicMax(&s_fin[k], v);
    }
    __syncthreads();

    if (threadIdx.x == 0) {
        float best = 0.0f;
        int   bidx = 0;
#pragma unroll
        for (int k = 0; k < NCAND; k++) {
            float md  = __uint_as_float(s_fin[k]);
            int   L   = LENS[k];
            float raw = (float)((double)(NTOT / L) / (double)L);
            float eff = (md < 0.01f) ? raw : 0.0f;
            if (k < out_size)      out[k]      = md;
            if (20 + k < out_size) out[20 + k] = eff;
            if (eff > best) { best = eff; bidx = k; }  // first max, like jnp.argmax
        }
        if (out_size > 40) out[40] = (float)bidx;
        if (out_size > 41) out[41] = best;
    }
}

// ---------------------------------------------------------------------------
extern "C" void kernel_launch(void* const* d_in, const int* in_sizes, int n_in,
                              void* d_out, int out_size) {
    const float* x = (const float*)d_in[0];
    float* out = (float*)d_out;

    dim3 grid(NBX, RSPLIT);
    pm_fused<<<grid, 256>>>((const float4*)x, out, out_size);
}